// round 12
// baseline (speedup 1.0000x reference)
#include <cuda_runtime.h>
#include <cuda_fp16.h>
#include <math.h>
#include <stdint.h>

#define T     128
#define H     1024
#define INTER 4096
#define NE    8
#define NKCH  32          // 32 K-chunks of 32 = K depth 1024 per CTA

// ---------------- device-global scratch ----------------
__device__ int    g_cnt[NE];
__device__ int    g_tok[NE][T];
__device__ float  g_coef[NE][T];            // pad slots never written -> stay 0
__device__ int    g_rb_e[40];               // row-block -> expert
__device__ int    g_rb_m[40];               // row-block -> m0
__device__ int    g_nrb;                    // number of row-blocks
__device__ int    g_work1;                  // fc1 work counter
// chunk-packed fp16 activations: [e][k-chunk][m][32 k]
__device__ __half g_xg[NE][32][T][32];      // gathered token rows (2 MB)
__device__ __half g_act[NE][128][T][32];    // coef-scaled swiglu output (8.4 MB)

// ---------------- smem layout (dynamic) ----------------
// [0,512) coefs/toks   [512,516) work broadcast
// stages: 3 x (A 2KB + B 8KB), fp16, 2 logical rows per 128B line,
// 16B unit u of packed row p stored at u ^ (p & 7).
#define ST_OFF   1024
#define STG_B    2048
#define STAGEB   10240
#define SMEM_BYTES (1024 + 3 * STAGEB)   // 31744

// ---------------- PTX helpers ----------------
static __device__ __forceinline__ uint32_t smem_u32(const void* p){
    uint32_t a;
    asm("{ .reg .u64 t; cvta.to.shared.u64 t, %1; cvt.u32.u64 %0, t; }" : "=r"(a) : "l"(p));
    return a;
}
#define CP16(d, s)  asm volatile("cp.async.cg.shared.global [%0], [%1], 16;" :: "r"(d), "l"(s) : "memory")
#define CP_COMMIT() asm volatile("cp.async.commit_group;" ::: "memory")
#define CP_WAIT1()  asm volatile("cp.async.wait_group 1;" ::: "memory")
#define CP_WAIT0()  asm volatile("cp.async.wait_group 0;" ::: "memory")

static __device__ __forceinline__ uint32_t pack_h2(float lo, float hi){
    uint32_t r;
    asm("cvt.rn.f16x2.f32 %0, %1, %2;" : "=r"(r) : "f"(hi), "f"(lo));
    return r;
}
static __device__ __forceinline__ void sts8h(uint32_t addr, float4 v){
    uint32_t h0 = pack_h2(v.x, v.y), h1 = pack_h2(v.z, v.w);
    asm volatile("st.shared.v2.b32 [%0], {%1,%2};"
                 :: "r"(addr), "r"(h0), "r"(h1) : "memory");
}
#define LDM4(r, addr) \
    asm volatile("ldmatrix.sync.aligned.m8n8.x4.shared.b16 {%0,%1,%2,%3}, [%4];" \
        : "=r"((r)[0]), "=r"((r)[1]), "=r"((r)[2]), "=r"((r)[3]) : "r"(addr))

static __device__ __forceinline__ void mma16(float* d, const uint32_t* a, uint32_t b0, uint32_t b1){
    asm volatile("mma.sync.aligned.m16n8k16.row.col.f32.f16.f16.f32 "
        "{%0,%1,%2,%3}, {%4,%5,%6,%7}, {%8,%9}, {%0,%1,%2,%3};"
        : "+f"(d[0]), "+f"(d[1]), "+f"(d[2]), "+f"(d[3])
        : "r"(a[0]), "r"(a[1]), "r"(a[2]), "r"(a[3]), "r"(b0), "r"(b1));
}

// ---------------- kernel 1: routing + work-list build ----------------
__global__ void route_kernel(const float* __restrict__ routing) {
    __shared__ int s_cnt[NE];
    int t = threadIdx.x;
    if (t < NE) s_cnt[t] = 0;
    __syncthreads();
    float r[NE];
#pragma unroll
    for (int e = 0; e < NE; e++) r[e] = routing[t * NE + e];
    int i0 = 0;
#pragma unroll
    for (int e = 1; e < NE; e++) if (r[e] > r[i0]) i0 = e;
    int i1 = (i0 == 0) ? 1 : 0;
#pragma unroll
    for (int e = 0; e < NE; e++) if (e != i0 && r[e] > r[i1]) i1 = e;
    float d  = expf(r[i1] - r[i0]);
    float s0 = 1.0f / (1.0f + d);
    float s1 = d / (1.0f + d);
    int p0 = atomicAdd(&s_cnt[i0], 1);
    int p1 = atomicAdd(&s_cnt[i1], 1);
    g_tok[i0][p0] = t;  g_coef[i0][p0] = s0;
    g_tok[i1][p1] = t;  g_coef[i1][p1] = s1;
    __syncthreads();
    if (t < NE) g_cnt[t] = s_cnt[t];
    if (t == 0) {
        int n = 0;
        for (int e = 0; e < NE; e++)
            for (int m0 = 0; m0 < s_cnt[e]; m0 += 32) {
                g_rb_e[n] = e; g_rb_m[n] = m0; n++;
            }
        g_nrb = n;
        g_work1 = 0;
    }
}

// ---------------- kernel 2: gather token rows (fp16, chunk-packed) + zero out ----
// 1024 blocks x 128 threads; block = one (e, m) row + zeros 128 floats of out.
__global__ void gather_x_kernel(const float* __restrict__ x, float* __restrict__ out) {
    int bid = blockIdx.x;
    int e = bid >> 7, m = bid & 127;
    int t = threadIdx.x;
    out[bid * 128 + t] = 0.0f;
    int tok = (m < g_cnt[e]) ? g_tok[e][m] : 0;
    const float4* src = (const float4*)(x + (size_t)tok * H);
    float4 v0 = src[2 * t];
    float4 v1 = src[2 * t + 1];
    uint4 o;
    o.x = pack_h2(v0.x, v0.y); o.y = pack_h2(v0.z, v0.w);
    o.z = pack_h2(v1.x, v1.y); o.w = pack_h2(v1.z, v1.w);
    *(uint4*)&g_xg[e][t >> 2][m][(t & 3) * 8] = o;
}

// ================= GEMM machinery =================
// CTA tile M=32 x N=128 x Kchunk=32 (2 k16 steps); 8 warps 2(M) x 4(N), warp tile 16x32.
static __device__ __forceinline__ void compute_chunk(
        uint32_t aAf, uint32_t aBf0, uint32_t aBf1, float (&acc)[4][4]) {
#pragma unroll
    for (int s = 0; s < 2; s++) {
        uint32_t x = s << 5;
        uint32_t a[4], b0[4], b1[4];
        LDM4(a,  aAf  ^ x);
        LDM4(b0, aBf0 ^ x);
        LDM4(b1, aBf1 ^ x);
        mma16(acc[0], a, b0[0], b0[1]);
        mma16(acc[1], a, b0[2], b0[3]);
        mma16(acc[2], a, b1[0], b1[1]);
        mma16(acc[3], a, b1[2], b1[3]);
    }
}

#define GEMM_SETUP() \
    int tid = threadIdx.x, wid = tid >> 5, lane = tid & 31; \
    int wm = wid >> 2, wn = wid & 3; \
    uint32_t smemA = smem_u32(smem) + ST_OFF; \
    uint32_t smemB = smemA + STG_B; \
    int car = tid >> 2, cau = tid & 3; \
    uint32_t capr = (uint32_t)(car >> 1); \
    uint32_t aAdst = smemA + capr * 128 + \
        ((((uint32_t)(4 * (car & 1) + cau)) ^ (capr & 7)) << 4); \
    int bro = wid * 16 + ((tid & 31) >> 3); \
    int bul = tid & 7; \
    uint32_t bu2 = (uint32_t)(bul >> 1), bhalf = (uint32_t)(bul & 1); \
    uint32_t sb[4]; \
    _Pragma("unroll") for (int _j = 0; _j < 4; _j++) { \
        uint32_t _r = (uint32_t)(bro + 4 * _j), _p = _r >> 1; \
        sb[_j] = smemB + _p * 128 + \
            ((((uint32_t)(4 * (_r & 1)) + bu2) ^ (_p & 7)) << 4) + bhalf * 8; \
    } \
    int ls = lane & 7, h3 = (lane >> 3) & 1, h4 = (lane >> 4) & 1; \
    int am = wm * 16 + ls + 8 * h3; \
    uint32_t apf = (uint32_t)(am >> 1); \
    uint32_t aAf = smemA + apf * 128 + ((((uint32_t)(4 * (am & 1) + h4)) ^ (apf & 7)) << 4); \
    int bnf = wn * 32 + ls + 8 * h4; \
    uint32_t bpf = (uint32_t)(bnf >> 1); \
    uint32_t aBf0 = smemB + bpf * 128 + ((((uint32_t)(4 * (bnf & 1) + h3)) ^ (bpf & 7)) << 4); \
    uint32_t aBf1 = aBf0 + 1024; \
    float4 rb0, rb1, rb2, rb3; \
    float acc[4][4];

#define ACC_ZERO() \
    _Pragma("unroll") for (int _j = 0; _j < 4; _j++) \
    _Pragma("unroll") for (int _q = 0; _q < 4; _q++) acc[_j][_q] = 0.0f;

#define CPA(i, st) \
    if (tid < 128) CP16(aAdst + (st) * STAGEB, aglob + (size_t)(i) * 4096)

#define LDGB(i) do { \
        rb0 = *(const float4*)(bglob + (i) * 32); \
        rb1 = *(const float4*)(bglob + 4  * BRS + (i) * 32); \
        rb2 = *(const float4*)(bglob + 8  * BRS + (i) * 32); \
        rb3 = *(const float4*)(bglob + 12 * BRS + (i) * 32); \
    } while (0)

#define STSB(st) do { \
        sts8h(sb[0] + (st) * STAGEB, rb0); \
        sts8h(sb[1] + (st) * STAGEB, rb1); \
        sts8h(sb[2] + (st) * STAGEB, rb2); \
        sts8h(sb[3] + (st) * STAGEB, rb3); \
    } while (0)

#define GEMM_MAINLOOP() \
    LDGB(0); CPA(0, 0); CP_COMMIT(); \
    STSB(0); \
    LDGB(1); CPA(1, 1); CP_COMMIT(); \
    { \
        int stc = 0; \
        for (int i = 0; i < NKCH; i++) { \
            if (i < NKCH - 1) { CP_WAIT1(); } else { CP_WAIT0(); } \
            __syncthreads(); \
            int st1 = stc + 1; if (st1 == 3) st1 = 0; \
            int st2 = st1 + 1; if (st2 == 3) st2 = 0; \
            if (i + 1 < NKCH) STSB(st1); \
            if (i + 2 < NKCH) { LDGB(i + 2); CPA(i + 2, st2); CP_COMMIT(); } \
            uint32_t so = (uint32_t)stc * STAGEB; \
            compute_chunk(aAf + so, aBf0 + so, aBf1 + so, acc); \
            stc = st1; \
        } \
    }

// ---------------- kernel 3: fc1 — persistent, work-stealing ----------------
// grid 448 CTAs; items w in [0, 64*R): nt = w / R (consecutive items share the
// weight block -> concurrent L2 reuse), row-block = w % R.
__global__ void __launch_bounds__(256, 3) fc1_mma(const float* __restrict__ w1) {
    extern __shared__ __align__(1024) char smem[];
    float* coefs = (float*)smem;
    int*   swk   = (int*)(smem + 512);

    GEMM_SETUP();

    int R = g_nrb;
    int total = 64 * R;

    for (;;) {
        if (tid == 0) *swk = atomicAdd(&g_work1, 1);
        __syncthreads();
        int w = *swk;
        if (w >= total) break;
        int nt  = w / R;
        int rbi = w - nt * R;
        int e   = g_rb_e[rbi];
        int m0g = g_rb_m[rbi];
        int n0  = nt * 64;

        if (tid < 32) coefs[tid] = g_coef[e][m0g + tid];   // pads = 0

        const __half* aglob = &g_xg[e][0][m0g][0] + tid * 8;
        const intptr_t BRS = H;
        int wrow0 = (bro < 64) ? (n0 + bro) : (INTER + n0 + (bro - 64));
        const float* bglob = w1 + (size_t)e * (2 * INTER) * H + (size_t)wrow0 * H + bul * 4;

        ACC_ZERO();
        GEMM_MAINLOOP();

        // ---- epilogue: exchange via smem, swiglu + coef, fp16 chunk-packed store ----
        __syncthreads();
        float* buf = (float*)(smem + ST_OFF);   // 32 x 132 fp32
        int g0 = lane >> 2, t4 = lane & 3;
#pragma unroll
        for (int nf = 0; nf < 4; nf++) {
            int j  = wn * 32 + nf * 8 + 2 * t4;
            int r0 = wm * 16 + g0;
            buf[r0 * 132 + j]           = acc[nf][0];
            buf[r0 * 132 + j + 1]       = acc[nf][1];
            buf[(r0 + 8) * 132 + j]     = acc[nf][2];
            buf[(r0 + 8) * 132 + j + 1] = acc[nf][3];
        }
        __syncthreads();
        {
            int m  = tid >> 3;
            int cb = (tid & 7) * 8;
            float c = coefs[m];
            const float* row = &buf[m * 132];
            float o[8];
#pragma unroll
            for (int q = 0; q < 8; q++) {
                float u = row[cb + q];
                float g = row[64 + cb + q];
                o[q] = c * (u / (1.0f + __expf(-u))) * g;
            }
            uint4 pk;
            pk.x = pack_h2(o[0], o[1]); pk.y = pack_h2(o[2], o[3]);
            pk.z = pack_h2(o[4], o[5]); pk.w = pack_h2(o[6], o[7]);
            *(uint4*)&g_act[e][(n0 + cb) >> 5][m0g + m][cb & 31] = pk;
        }
    }
}

// ---------------- kernel 4: fc2 GEMM (4-way K-split) + scatter-add ----------------
// grid (4, 32, NE): x = m-tile (fastest), y = n-tile(8) x k-slice(4).
__global__ void __launch_bounds__(256, 3) fc2_mma(const float* __restrict__ w2,
                                                  float* __restrict__ out) {
    extern __shared__ __align__(1024) char smem[];
    int* toks = (int*)smem;

    int e   = blockIdx.z;
    int cnt = g_cnt[e];
    int m0g = blockIdx.x * 32;
    if (m0g >= cnt) return;
    int n0    = (blockIdx.y >> 2) * 128;
    int kbase = (blockIdx.y & 3) * 1024;

    GEMM_SETUP();

    if (tid < 32) toks[tid] = (m0g + tid < cnt) ? g_tok[e][m0g + tid] : 0;

    const __half* aglob = &g_act[e][kbase >> 5][m0g][0] + tid * 8;
    const intptr_t BRS = INTER;
    const float* bglob = w2 + (size_t)e * H * INTER + (size_t)(n0 + bro) * INTER + kbase + bul * 4;

    ACC_ZERO();
    GEMM_MAINLOOP();

    int g0 = lane >> 2, t4 = lane & 3;
    int r0 = wm * 16 + g0;
#pragma unroll
    for (int nf = 0; nf < 4; nf++) {
        int n = n0 + wn * 32 + nf * 8 + 2 * t4;
        if (m0g + r0 < cnt) {
            float* o = out + (size_t)toks[r0] * H + n;
            atomicAdd(o,     acc[nf][0]);
            atomicAdd(o + 1, acc[nf][1]);
        }
        if (m0g + r0 + 8 < cnt) {
            float* o = out + (size_t)toks[r0 + 8] * H + n;
            atomicAdd(o,     acc[nf][2]);
            atomicAdd(o + 1, acc[nf][3]);
        }
    }
}

// ---------------- launch ----------------
extern "C" void kernel_launch(void* const* d_in, const int* in_sizes, int n_in,
                              void* d_out, int out_size) {
    const float* x       = (const float*)d_in[0];   // [128, 1024]
    const float* routing = (const float*)d_in[1];   // [128, 8]
    const float* w1      = (const float*)d_in[2];   // [8, 8192, 1024]
    const float* w2      = (const float*)d_in[3];   // [8, 1024, 4096]
    float* out = (float*)d_out;                     // [128, 1024]

    cudaFuncSetAttribute(fc1_mma, cudaFuncAttributeMaxDynamicSharedMemorySize, SMEM_BYTES);
    cudaFuncSetAttribute(fc2_mma, cudaFuncAttributeMaxDynamicSharedMemorySize, SMEM_BYTES);

    route_kernel<<<1, T>>>(routing);
    gather_x_kernel<<<NE * T, 128>>>(x, out);
    fc1_mma<<<448, 256, SMEM_BYTES>>>(w1);
    fc2_mma<<<dim3(4, 32, NE), 256, SMEM_BYTES>>>(w2, out);
}

// round 13
// speedup vs baseline: 1.1016x; 1.1016x over previous
#include <cuda_runtime.h>
#include <math.h>
#include <stdint.h>

#define T     128
#define H     1024
#define INTER 4096
#define NE    8
#define NKCH  32          // 32 K-chunks of 32 = K depth 1024 per CTA

// ---------------- device-global scratch ----------------
__device__ int   g_cnt[NE];
__device__ int   g_tok[NE][T];
__device__ float g_coef[NE][T];           // pad slots never written -> stay 0
// chunk-packed tf32-rounded fp32 activations: [e][k-chunk][m][32 k]
__device__ float g_xg[NE][32][T][32];     // gathered token rows (4.2 MB)
__device__ float g_act[NE][128][T][32];   // coef-scaled swiglu output (16.8 MB)

// ---------------- smem layout (dynamic) ----------------
// [0,512) coefs/toks
// stages: 3 x (A 4KB + B 16KB) fp32 tiles, 128B rows,
// 16B unit u of row r stored at u ^ (r & 7).
#define ST_OFF   1024
#define STG_B    4096
#define STAGEB   20480
#define SMEM_BYTES (1024 + 3 * STAGEB)   // 62464

// ---------------- PTX helpers ----------------
static __device__ __forceinline__ uint32_t smem_u32(const void* p){
    uint32_t a;
    asm("{ .reg .u64 t; cvta.to.shared.u64 t, %1; cvt.u32.u64 %0, t; }" : "=r"(a) : "l"(p));
    return a;
}
#define CP16(d, s)  asm volatile("cp.async.cg.shared.global [%0], [%1], 16;" :: "r"(d), "l"(s) : "memory")
#define CP_COMMIT() asm volatile("cp.async.commit_group;" ::: "memory")
#define CP_WAIT1()  asm volatile("cp.async.wait_group 1;" ::: "memory")

static __device__ __forceinline__ uint32_t f2tf(float x){
    uint32_t r; asm("cvt.rna.tf32.f32 %0, %1;" : "=r"(r) : "f"(x)); return r;
}
static __device__ __forceinline__ uint32_t rnd_bits(uint32_t b){
    return f2tf(__uint_as_float(b));
}
#define LDM4(r, addr) \
    asm volatile("ldmatrix.sync.aligned.m8n8.x4.shared.b16 {%0,%1,%2,%3}, [%4];" \
        : "=r"((r)[0]), "=r"((r)[1]), "=r"((r)[2]), "=r"((r)[3]) : "r"(addr))

static __device__ __forceinline__ void mma8(float* d, const uint32_t* a, uint32_t b0, uint32_t b1){
    asm volatile("mma.sync.aligned.m16n8k8.row.col.f32.tf32.tf32.f32 "
        "{%0,%1,%2,%3}, {%4,%5,%6,%7}, {%8,%9}, {%0,%1,%2,%3};"
        : "+f"(d[0]), "+f"(d[1]), "+f"(d[2]), "+f"(d[3])
        : "r"(a[0]), "r"(a[1]), "r"(a[2]), "r"(a[3]), "r"(b0), "r"(b1));
}

// ---------------- kernel 1: routing ----------------
__global__ void route_kernel(const float* __restrict__ routing) {
    __shared__ int s_cnt[NE];
    int t = threadIdx.x;
    if (t < NE) s_cnt[t] = 0;
    __syncthreads();
    float r[NE];
#pragma unroll
    for (int e = 0; e < NE; e++) r[e] = routing[t * NE + e];
    int i0 = 0;
#pragma unroll
    for (int e = 1; e < NE; e++) if (r[e] > r[i0]) i0 = e;
    int i1 = (i0 == 0) ? 1 : 0;
#pragma unroll
    for (int e = 0; e < NE; e++) if (e != i0 && r[e] > r[i1]) i1 = e;
    float d  = expf(r[i1] - r[i0]);
    float s0 = 1.0f / (1.0f + d);
    float s1 = d / (1.0f + d);
    int p0 = atomicAdd(&s_cnt[i0], 1);
    int p1 = atomicAdd(&s_cnt[i1], 1);
    g_tok[i0][p0] = t;  g_coef[i0][p0] = s0;
    g_tok[i1][p1] = t;  g_coef[i1][p1] = s1;
    __syncthreads();
    if (t < NE) g_cnt[t] = s_cnt[t];
}

// ---------------- kernel 2: gather token rows (tf32-rounded, chunk-packed) + zero out ----
// 1024 blocks x 128 threads; block = one (e, m) row + zeros 128 floats of out.
__global__ void gather_x_kernel(const float* __restrict__ x, float* __restrict__ out) {
    int bid = blockIdx.x;
    int e = bid >> 7, m = bid & 127;
    int t = threadIdx.x;
    out[bid * 128 + t] = 0.0f;
    int tok = (m < g_cnt[e]) ? g_tok[e][m] : 0;
    const float4* src = (const float4*)(x + (size_t)tok * H);
    float4 v0 = src[2 * t];
    float4 v1 = src[2 * t + 1];
    uint4 o0, o1;
    o0.x = f2tf(v0.x); o0.y = f2tf(v0.y); o0.z = f2tf(v0.z); o0.w = f2tf(v0.w);
    o1.x = f2tf(v1.x); o1.y = f2tf(v1.y); o1.z = f2tf(v1.z); o1.w = f2tf(v1.w);
    uint4* dst = (uint4*)&g_xg[e][t >> 2][m][(t & 3) * 8];
    dst[0] = o0; dst[1] = o1;
}

// ================= GEMM machinery =================
// CTA tile M=32 x N=128 x Kchunk=32 (4 tf32 k8 steps); 8 warps 2(M) x 4(N),
// warp tile 16x32. fp32 tiles in smem; A pre-rounded, B rounded in fragments.
static __device__ __forceinline__ void compute_chunk(
        uint32_t aAf, uint32_t aBf0, uint32_t aBf1, float (&acc)[4][4]) {
#pragma unroll
    for (int ks = 0; ks < 4; ks++) {
        uint32_t x = ks << 5;
        uint32_t a[4], b0[4], b1[4];
        LDM4(a,  aAf  ^ x);
        LDM4(b0, aBf0 ^ x);
        LDM4(b1, aBf1 ^ x);
#pragma unroll
        for (int j = 0; j < 4; j++) { b0[j] = rnd_bits(b0[j]); b1[j] = rnd_bits(b1[j]); }
        mma8(acc[0], a, b0[0], b1[0]);
        mma8(acc[1], a, b0[1], b1[1]);
        mma8(acc[2], a, b0[2], b1[2]);
        mma8(acc[3], a, b0[3], b1[3]);
    }
}

#define GEMM_SETUP() \
    int tid = threadIdx.x, wid = tid >> 5, lane = tid & 31; \
    int wm = wid >> 2, wn = wid & 3; \
    uint32_t smemA = smem_u32(smem) + ST_OFF; \
    uint32_t smemB = smemA + STG_B; \
    /* A cp.async: thread t -> row t>>3 (0-31), 16B unit t&7; swizzled dst */ \
    int car = tid >> 3, cau = tid & 7; \
    uint32_t aAdst = smemA + (uint32_t)car * 128 + (((uint32_t)cau ^ (car & 7)) << 4); \
    /* B cp.async: warp w rows w*16+{0..3}+4j, unit tid&7; coalesced src */ \
    int bro = wid * 16 + ((tid >> 3) & 3); \
    int bul = tid & 7; \
    uint32_t sb[4]; \
    _Pragma("unroll") for (int _j = 0; _j < 4; _j++) { \
        uint32_t _r = (uint32_t)(bro + 4 * _j); \
        sb[_j] = smemB + _r * 128 + (((uint32_t)bul ^ (_r & 7)) << 4); \
    } \
    /* fragment addresses */ \
    int ls = lane & 7, h3 = (lane >> 3) & 1, h4 = (lane >> 4) & 1; \
    uint32_t amr = (uint32_t)(wm * 16 + 8 * h3 + ls); \
    uint32_t aAf = smemA + amr * 128 + (((uint32_t)h4 ^ ls) << 4); \
    uint32_t bnr = (uint32_t)(wn * 32 + (lane >> 3) * 8 + ls); \
    uint32_t aBf0 = smemB + bnr * 128 + (((uint32_t)0 ^ ls) << 4); \
    uint32_t aBf1 = smemB + bnr * 128 + (((uint32_t)1 ^ ls) << 4); \
    float acc[4][4]; \
    _Pragma("unroll") for (int _j = 0; _j < 4; _j++) \
    _Pragma("unroll") for (int _q = 0; _q < 4; _q++) acc[_j][_q] = 0.0f;

#define CPA(i, st) \
    CP16(aAdst + (st) * STAGEB, aglob + (size_t)(i) * 4096)

#define CPB(i, st) do { \
        CP16(sb[0] + (st) * STAGEB, bglob + (i) * 32); \
        CP16(sb[1] + (st) * STAGEB, bglob + 4  * BRS + (i) * 32); \
        CP16(sb[2] + (st) * STAGEB, bglob + 8  * BRS + (i) * 32); \
        CP16(sb[3] + (st) * STAGEB, bglob + 12 * BRS + (i) * 32); \
    } while (0)

// 3 stages, depth-2 cp.async pipeline, 1 barrier per chunk.
#define GEMM_MAINLOOP() \
    CPA(0, 0); CPB(0, 0); CP_COMMIT(); \
    CPA(1, 1); CPB(1, 1); CP_COMMIT(); \
    { \
        int stc = 0; \
        for (int i = 0; i < NKCH; i++) { \
            CP_WAIT1(); \
            __syncthreads(); \
            int st2 = stc + 2; if (st2 >= 3) st2 -= 3; \
            if (i + 2 < NKCH) { CPA(i + 2, st2); CPB(i + 2, st2); } \
            CP_COMMIT(); \
            uint32_t so = (uint32_t)stc * STAGEB; \
            compute_chunk(aAf + so, aBf0 + so, aBf1 + so, acc); \
            if (++stc == 3) stc = 0; \
        } \
    }

// ---------------- kernel 3: fc1 GEMM + fused swiglu + coef fold ----------------
// grid (4, 64, NE): x = m-tile (fastest -> concurrent L2 weight reuse), y = 64-ch n-tile.
// B tile rows 0-63 = up channels, 64-127 = gate channels.
__global__ void __launch_bounds__(256, 3) fc1_mma(const float* __restrict__ w1) {
    extern __shared__ __align__(1024) char smem[];
    float* coefs = (float*)smem;

    int e   = blockIdx.z;
    int cnt = g_cnt[e];
    int m0g = blockIdx.x * 32;
    if (m0g >= cnt) return;
    int n0  = blockIdx.y * 64;

    GEMM_SETUP();

    if (tid < 32) coefs[tid] = g_coef[e][m0g + tid];   // pads = 0

    const float* aglob = &g_xg[e][0][m0g][0] + (car * 32 + cau * 4);
    const intptr_t BRS = H;
    int wrow0 = (bro < 64) ? (n0 + bro) : (INTER + n0 + (bro - 64));
    const float* bglob = w1 + (size_t)e * (2 * INTER) * H + (size_t)wrow0 * H + bul * 4;

    GEMM_MAINLOOP();

    // ---- epilogue: exchange via smem, swiglu + coef, tf32-rounded store to g_act ----
    __syncthreads();
    float* buf = (float*)(smem + ST_OFF);   // 32 x 132 fp32
    int g0 = lane >> 2, t4 = lane & 3;
#pragma unroll
    for (int nf = 0; nf < 4; nf++) {
        int j  = wn * 32 + nf * 8 + 2 * t4;
        int r0 = wm * 16 + g0;
        buf[r0 * 132 + j]           = acc[nf][0];
        buf[r0 * 132 + j + 1]       = acc[nf][1];
        buf[(r0 + 8) * 132 + j]     = acc[nf][2];
        buf[(r0 + 8) * 132 + j + 1] = acc[nf][3];
    }
    __syncthreads();
    {
        int m  = tid >> 3;
        int cb = (tid & 7) * 8;
        float c = coefs[m];
        const float* row = &buf[m * 132];
        uint32_t w[8];
#pragma unroll
        for (int q = 0; q < 8; q++) {
            float u = row[cb + q];
            float g = row[64 + cb + q];
            w[q] = f2tf(c * (u / (1.0f + __expf(-u))) * g);
        }
        uint4* dst = (uint4*)&g_act[e][(n0 + cb) >> 5][m0g + m][cb & 31];
        uint4 p0, p1;
        p0.x = w[0]; p0.y = w[1]; p0.z = w[2]; p0.w = w[3];
        p1.x = w[4]; p1.y = w[5]; p1.z = w[6]; p1.w = w[7];
        dst[0] = p0; dst[1] = p1;
    }
}

// ---------------- kernel 4: fc2 GEMM (4-way K-split) + scatter-add ----------------
// grid (4, 32, NE): x = m-tile (fastest), y = n-tile(8) x k-slice(4).
__global__ void __launch_bounds__(256, 3) fc2_mma(const float* __restrict__ w2,
                                                  float* __restrict__ out) {
    extern __shared__ __align__(1024) char smem[];
    int* toks = (int*)smem;

    int e   = blockIdx.z;
    int cnt = g_cnt[e];
    int m0g = blockIdx.x * 32;
    if (m0g >= cnt) return;
    int n0    = (blockIdx.y >> 2) * 128;
    int kbase = (blockIdx.y & 3) * 1024;

    GEMM_SETUP();

    if (tid < 32) toks[tid] = (m0g + tid < cnt) ? g_tok[e][m0g + tid] : 0;

    const float* aglob = &g_act[e][kbase >> 5][m0g][0] + (car * 32 + cau * 4);
    const intptr_t BRS = INTER;
    const float* bglob = w2 + (size_t)e * H * INTER + (size_t)(n0 + bro) * INTER + kbase + bul * 4;

    GEMM_MAINLOOP();

    int g0 = lane >> 2, t4 = lane & 3;
    int r0 = wm * 16 + g0;
#pragma unroll
    for (int nf = 0; nf < 4; nf++) {
        int n = n0 + wn * 32 + nf * 8 + 2 * t4;
        if (m0g + r0 < cnt) {
            float* o = out + (size_t)toks[r0] * H + n;
            atomicAdd(o,     acc[nf][0]);
            atomicAdd(o + 1, acc[nf][1]);
        }
        if (m0g + r0 + 8 < cnt) {
            float* o = out + (size_t)toks[r0 + 8] * H + n;
            atomicAdd(o,     acc[nf][2]);
            atomicAdd(o + 1, acc[nf][3]);
        }
    }
}

// ---------------- launch ----------------
extern "C" void kernel_launch(void* const* d_in, const int* in_sizes, int n_in,
                              void* d_out, int out_size) {
    const float* x       = (const float*)d_in[0];   // [128, 1024]
    const float* routing = (const float*)d_in[1];   // [128, 8]
    const float* w1      = (const float*)d_in[2];   // [8, 8192, 1024]
    const float* w2      = (const float*)d_in[3];   // [8, 1024, 4096]
    float* out = (float*)d_out;                     // [128, 1024]

    cudaFuncSetAttribute(fc1_mma, cudaFuncAttributeMaxDynamicSharedMemorySize, SMEM_BYTES);
    cudaFuncSetAttribute(fc2_mma, cudaFuncAttributeMaxDynamicSharedMemorySize, SMEM_BYTES);

    route_kernel<<<1, T>>>(routing);
    gather_x_kernel<<<NE * T, 128>>>(x, out);
    fc1_mma<<<dim3(4, 64, NE), 256, SMEM_BYTES>>>(w1);
    fc2_mma<<<dim3(4, 32, NE), 256, SMEM_BYTES>>>(w2, out);
}